// round 17
// baseline (speedup 1.0000x reference)
#include <cuda_runtime.h>
#include <cuda_bf16.h>
#include <cuda_fp16.h>
#include <math.h>
#include <stdint.h>

// ---------------------------------------------------------------------------
// GCN 2-layer forward. R16: (a) GEMM1 cp.async double-buffered at 2 CTA/SM
// (fp32 A staged in smem, fragment-side fp16 convert); (b) CSR build forked
// onto a side stream, overlapped with GEMM1 via capture fork-join.
// ---------------------------------------------------------------------------

#define NMAX 100000
#define EMAX 1600000
#define FIN  512
#define HID  128
#define NCLS 40
#define NBLK ((NMAX + 1023) / 1024)

typedef unsigned long long ull;

// --------------------------- device scratch --------------------------------
__device__ int   g_is64;
__device__ int   g_cnt[NMAX];
__device__ int   g_off[NMAX + 1];
__device__ int   g_cur[NMAX];
__device__ float g_dis[NMAX];
__device__ int   g_blksum[NBLK];
__device__ int   g_blkoff[NBLK];
__device__ int   g_esrc[EMAX];
__device__ float g_enrm[EMAX];
__device__ __align__(128) __half g_w1h[(size_t)HID * FIN];          // W1^T fp16
__device__ __align__(128) __half g_w2t[(size_t)NCLS * HID];         // W2^T fp16
__device__ __align__(128) __half2 g_h1f[(size_t)NMAX * (HID / 2)];  // x@W1
__device__ __align__(128) __half2 g_a1f[(size_t)NMAX * (HID / 2)];  // relu(agg)
__device__ __align__(128) __half2 g_h2f[(size_t)NMAX * (NCLS / 2)]; // a1@W2

// ------------------- side stream for CSR build (created once) --------------
struct StreamEnv {
    cudaStream_t s1 = 0;
    cudaEvent_t  e1 = 0, e2 = 0;
    StreamEnv() {
        cudaStreamCreateWithFlags(&s1, cudaStreamNonBlocking);
        cudaEventCreateWithFlags(&e1, cudaEventDisableTiming);
        cudaEventCreateWithFlags(&e2, cudaEventDisableTiming);
    }
};
static StreamEnv g_se;

// --------------------------- helpers ---------------------------------------
__device__ __forceinline__ int load_idx(const int* __restrict__ p, long long slot, int is64) {
    return is64 ? p[2 * slot] : p[slot];
}
__global__ void k_probe(const unsigned* __restrict__ p) {
    unsigned nz = 0;
    for (int i = 1; i < 256; i += 2) nz |= p[i];
    g_is64 = (nz == 0u) ? 1 : 0;
}
__device__ __forceinline__ unsigned pack_h2(float x, float y) {
    __half hx = __float2half_rn(x), hy = __float2half_rn(y);
    return (unsigned)__half_as_ushort(hx) | ((unsigned)__half_as_ushort(hy) << 16);
}
__device__ __forceinline__ float2 u32_as_f2h(unsigned u) {
    __half2 h = *reinterpret_cast<__half2*>(&u);
    return __half22float2(h);
}
__device__ __forceinline__ uint32_t smem_u32(const void* p) {
    uint32_t a;
    asm("{ .reg .u64 t; cvta.to.shared.u64 t, %1; cvt.u32.u64 %0, t; }" : "=r"(a) : "l"(p));
    return a;
}
__device__ __forceinline__ void cpa16(uint32_t dst, const void* src) {
    asm volatile("cp.async.cg.shared.global [%0], [%1], 16;" :: "r"(dst), "l"(src));
}
#define CP_COMMIT() asm volatile("cp.async.commit_group;" ::: "memory")
#define CP_WAIT0()  asm volatile("cp.async.wait_group 0;" ::: "memory")

#define MMA_F16(c, a, b0, b1)                                                    \
    asm volatile("mma.sync.aligned.m16n8k16.row.col.f32.f16.f16.f32 "            \
        "{%0,%1,%2,%3}, {%4,%5,%6,%7}, {%8,%9}, {%0,%1,%2,%3};"                  \
        : "+f"((c)[0]), "+f"((c)[1]), "+f"((c)[2]), "+f"((c)[3])                 \
        : "r"((a)[0]), "r"((a)[1]), "r"((a)[2]), "r"((a)[3]), "r"(b0), "r"(b1))

// --------------------------- CSR construction ------------------------------
__global__ void k_init(int n) {
    int i = blockIdx.x * blockDim.x + threadIdx.x;
    if (i < n) { g_cnt[i] = 0; g_cur[i] = 0; }
}
__global__ void k_hist(const int* __restrict__ ei, int E) {
    int e = blockIdx.x * blockDim.x + threadIdx.x;
    int is64 = g_is64;
    if (e < E) atomicAdd(&g_cnt[load_idx(ei, (long long)E + e, is64)], 1);
}
__global__ void k_scanA(int n) {
    __shared__ int sh[1024];
    int t = threadIdx.x;
    int i = blockIdx.x * 1024 + t;
    sh[t] = (i < n) ? g_cnt[i] : 0;
    __syncthreads();
#pragma unroll
    for (int d = 512; d > 0; d >>= 1) {
        if (t < d) sh[t] += sh[t + d];
        __syncthreads();
    }
    if (t == 0) g_blksum[blockIdx.x] = sh[0];
}
__global__ void k_scanB(int nb) {
    __shared__ int sh[128];
    int t = threadIdx.x;
    int v = (t < nb) ? g_blksum[t] : 0;
    sh[t] = v;
    __syncthreads();
#pragma unroll
    for (int d = 1; d < 128; d <<= 1) {
        int u = 0;
        if (t >= d) u = sh[t - d];
        __syncthreads();
        if (t >= d) sh[t] += u;
        __syncthreads();
    }
    if (t < nb) g_blkoff[t] = sh[t] - v;
}
__global__ void k_scanC(int n) {
    __shared__ int sh[1024];
    int t = threadIdx.x;
    int i = blockIdx.x * 1024 + t;
    int c = (i < n) ? g_cnt[i] : 0;
    sh[t] = c;
    __syncthreads();
#pragma unroll
    for (int d = 1; d < 1024; d <<= 1) {
        int u = 0;
        if (t >= d) u = sh[t - d];
        __syncthreads();
        if (t >= d) sh[t] += u;
        __syncthreads();
    }
    if (i < n) {
        int off = g_blkoff[blockIdx.x] + sh[t] - c;
        g_off[i] = off;
        g_dis[i] = rsqrtf((float)(c + 1));
        if (i == n - 1) g_off[n] = off + c;
    }
}
__global__ void k_scatter(const int* __restrict__ ei, int E) {
    int e = blockIdx.x * blockDim.x + threadIdx.x;
    int is64 = g_is64;
    if (e < E) {
        int s = load_idx(ei, e, is64);
        int d = load_idx(ei, (long long)E + e, is64);
        int p = g_off[d] + atomicAdd(&g_cur[d], 1);
        g_esrc[p] = s;
        g_enrm[p] = g_dis[s] * g_dis[d];
    }
}

// --------------- weight conversions (fp32 -> fp16, transposed) --------------
__global__ void k_wconv(const float* __restrict__ W1) {
    int i = blockIdx.x * blockDim.x + threadIdx.x;
    if (i < FIN * HID) {
        int k = i / HID, n = i % HID;
        g_w1h[(size_t)n * FIN + k] = __float2half_rn(W1[i]);
    }
}
__global__ void k_wconv2(const float* __restrict__ W2) {
    int i = blockIdx.x * blockDim.x + threadIdx.x;
    if (i < HID * NCLS) {
        int k = i / NCLS, n = i % NCLS;
        g_w2t[(size_t)n * HID + k] = __float2half_rn(W2[i]);
    }
}

// ---- GEMM1 fp16 mma.sync, cp.async double-buffered: [N,512]x[512,128] -----
// A staged fp32 in smem (stride 40 words; 16-lane phases -> conflict-free
// LDS.64), converted at fragment load. B fp16 (stride 40 halves, R13 proven).
// 2 buffers each; one sync per chunk; 60KB dyn smem -> 2 CTA/SM.
#define SA 40
#define G1SM (2 * 128 * 40 * 4 + 2 * 128 * 40 * 2)   // 61440 B

__global__ __launch_bounds__(256, 2) void k_gemm1_mma(const float* __restrict__ X, int M) {
    extern __shared__ char dyn[];
    float* sAf0 = (float*)dyn;
    float* sAf1 = sAf0 + 128 * SA;
    __half* sB0 = (__half*)(sAf1 + 128 * SA);
    __half* sB1 = sB0 + 128 * SA;

    int t    = threadIdx.x;
    int lane = t & 31;
    int wid  = t >> 5;
    int wm   = wid & 3;
    int wn   = wid >> 2;
    int blockRow = blockIdx.x * 128;

    // cp.async per-thread slots
    uint32_t aDst[2][4];
    const float* aSrc[4];
#pragma unroll
    for (int i = 0; i < 4; i++) {
        int f = t + i * 256;           // 0..1023
        int r = f >> 3;                // 0..127
        int sl = f & 7;                // 0..7 (16B units)
        int gr = blockRow + r;
        if (gr >= M) gr = M - 1;
        aSrc[i] = X + (size_t)gr * FIN + sl * 4;
        aDst[0][i] = smem_u32(&sAf0[r * SA + sl * 4]);
        aDst[1][i] = smem_u32(&sAf1[r * SA + sl * 4]);
    }
    uint32_t bDst[2][2];
    const __half* bSrc[2];
#pragma unroll
    for (int i = 0; i < 2; i++) {
        int f = t + i * 256;           // 0..511
        int n = f >> 2;                // 0..127
        int sl = f & 3;                // 0..3 (16B units)
        bSrc[i] = g_w1h + (size_t)n * FIN + sl * 8;
        bDst[0][i] = smem_u32(&sB0[n * SA + sl * 8]);
        bDst[1][i] = smem_u32(&sB1[n * SA + sl * 8]);
    }

    float acc[2][8][4];
#pragma unroll
    for (int mi = 0; mi < 2; mi++)
#pragma unroll
        for (int ni = 0; ni < 8; ni++)
#pragma unroll
            for (int c = 0; c < 4; c++) acc[mi][ni][c] = 0.f;

    const int lg = lane >> 2;
    const int lk = (lane & 3) * 2;

    // prologue: issue chunk 0 into buffer 0
#pragma unroll
    for (int i = 0; i < 4; i++) cpa16(aDst[0][i], aSrc[i]);
#pragma unroll
    for (int i = 0; i < 2; i++) cpa16(bDst[0][i], bSrc[i]);
    CP_COMMIT();

    for (int ch = 0; ch < 16; ch++) {
        CP_WAIT0();          // chunk ch data landed (only group outstanding)
        __syncthreads();     // all threads past MMA(ch-1); smem visible

        if (ch < 15) {       // overlap chunk ch+1 loads with MMA ch
            int b = (ch + 1) & 1;
            int off = (ch + 1) * 32;
#pragma unroll
            for (int i = 0; i < 4; i++) cpa16(aDst[b][i], aSrc[i] + off);
#pragma unroll
            for (int i = 0; i < 2; i++) cpa16(bDst[b][i], bSrc[i] + off);
            CP_COMMIT();
        }

        const float* Af = (ch & 1) ? sAf1 : sAf0;
        const __half* Bh = (ch & 1) ? sB1 : sB0;
#pragma unroll
        for (int kk = 0; kk < 2; kk++) {
            int k0 = kk * 16 + lk;
            uint32_t ah[2][4];
#pragma unroll
            for (int mi = 0; mi < 2; mi++) {
                int r0 = wm * 32 + mi * 16 + lg;
                float2 p0 = *(const float2*)&Af[r0 * SA + k0];
                float2 p1 = *(const float2*)&Af[(r0 + 8) * SA + k0];
                float2 p2 = *(const float2*)&Af[r0 * SA + k0 + 8];
                float2 p3 = *(const float2*)&Af[(r0 + 8) * SA + k0 + 8];
                ah[mi][0] = pack_h2(p0.x, p0.y);
                ah[mi][1] = pack_h2(p1.x, p1.y);
                ah[mi][2] = pack_h2(p2.x, p2.y);
                ah[mi][3] = pack_h2(p3.x, p3.y);
            }
#pragma unroll
            for (int ni = 0; ni < 8; ni++) {
                int c0 = wn * 64 + ni * 8 + lg;
                uint32_t b0 = *(const uint32_t*)&Bh[c0 * SA + k0];
                uint32_t b1 = *(const uint32_t*)&Bh[c0 * SA + k0 + 8];
#pragma unroll
                for (int mi = 0; mi < 2; mi++)
                    MMA_F16(acc[mi][ni], ah[mi], b0, b1);
            }
        }
    }

#pragma unroll
    for (int mi = 0; mi < 2; mi++) {
        int r0 = blockRow + wm * 32 + mi * 16 + (lane >> 2);
#pragma unroll
        for (int ni = 0; ni < 8; ni++) {
            int c2 = (wn * 64 + ni * 8 + (lane & 3) * 2) >> 1;
            if (r0 < M)
                g_h1f[(size_t)r0 * (HID / 2) + c2] = __floats2half2_rn(acc[mi][ni][0], acc[mi][ni][1]);
            if (r0 + 8 < M)
                g_h1f[(size_t)(r0 + 8) * (HID / 2) + c2] = __floats2half2_rn(acc[mi][ni][2], acc[mi][ni][3]);
        }
    }
}

// ------- Aggregation 1: warp/node, fp16 gather, x4-unrolled edge loop ------
__global__ void k_agg1(const float* __restrict__ b1, int n) {
    int w = (blockIdx.x * blockDim.x + threadIdx.x) >> 5;
    if (w >= n) return;
    int l = threadIdx.x & 31;

    float di = g_dis[w];
    float dself = di * di;

    const __half2* self = &g_h1f[(size_t)w * (HID / 2) + l * 2];
    float2 s0 = __half22float2(self[0]);
    float2 s1 = __half22float2(self[1]);
    float4 acc = make_float4(s0.x * dself, s0.y * dself, s1.x * dself, s1.y * dself);

    int beg = g_off[w], end = g_off[w + 1];
    int p = beg;
    for (; p + 4 <= end; p += 4) {
        int   s0i = g_esrc[p],     s1i = g_esrc[p + 1];
        int   s2i = g_esrc[p + 2], s3i = g_esrc[p + 3];
        float w0 = g_enrm[p],      w1 = g_enrm[p + 1];
        float w2 = g_enrm[p + 2],  w3 = g_enrm[p + 3];
        uint2 v0 = *(const uint2*)&g_h1f[(size_t)s0i * (HID / 2) + l * 2];
        uint2 v1 = *(const uint2*)&g_h1f[(size_t)s1i * (HID / 2) + l * 2];
        uint2 v2 = *(const uint2*)&g_h1f[(size_t)s2i * (HID / 2) + l * 2];
        uint2 v3 = *(const uint2*)&g_h1f[(size_t)s3i * (HID / 2) + l * 2];
        float2 a0 = u32_as_f2h(v0.x), b0v = u32_as_f2h(v0.y);
        float2 a1 = u32_as_f2h(v1.x), b1v = u32_as_f2h(v1.y);
        float2 a2 = u32_as_f2h(v2.x), b2v = u32_as_f2h(v2.y);
        float2 a3 = u32_as_f2h(v3.x), b3v = u32_as_f2h(v3.y);
        acc.x = fmaf(a0.x, w0, acc.x); acc.y = fmaf(a0.y, w0, acc.y);
        acc.z = fmaf(b0v.x, w0, acc.z); acc.w = fmaf(b0v.y, w0, acc.w);
        acc.x = fmaf(a1.x, w1, acc.x); acc.y = fmaf(a1.y, w1, acc.y);
        acc.z = fmaf(b1v.x, w1, acc.z); acc.w = fmaf(b1v.y, w1, acc.w);
        acc.x = fmaf(a2.x, w2, acc.x); acc.y = fmaf(a2.y, w2, acc.y);
        acc.z = fmaf(b2v.x, w2, acc.z); acc.w = fmaf(b2v.y, w2, acc.w);
        acc.x = fmaf(a3.x, w3, acc.x); acc.y = fmaf(a3.y, w3, acc.y);
        acc.z = fmaf(b3v.x, w3, acc.z); acc.w = fmaf(b3v.y, w3, acc.w);
    }
    for (; p < end; p++) {
        int   s  = g_esrc[p];
        float wt = g_enrm[p];
        uint2 v = *(const uint2*)&g_h1f[(size_t)s * (HID / 2) + l * 2];
        float2 f0 = u32_as_f2h(v.x);
        float2 f1 = u32_as_f2h(v.y);
        acc.x = fmaf(f0.x, wt, acc.x);
        acc.y = fmaf(f0.y, wt, acc.y);
        acc.z = fmaf(f1.x, wt, acc.z);
        acc.w = fmaf(f1.y, wt, acc.w);
    }
    float4 bb = *(const float4*)&b1[l * 4];
    acc.x = fmaxf(acc.x + bb.x, 0.f);
    acc.y = fmaxf(acc.y + bb.y, 0.f);
    acc.z = fmaxf(acc.z + bb.z, 0.f);
    acc.w = fmaxf(acc.w + bb.w, 0.f);
    uint2 o;
    o.x = pack_h2(acc.x, acc.y);
    o.y = pack_h2(acc.z, acc.w);
    *(uint2*)&g_a1f[(size_t)w * (HID / 2) + l * 2] = o;
}

// ---------- GEMM2 via mma.sync fp16: [N,128] x [128,40] -> g_h2f ----------
#define SB2 136

__global__ __launch_bounds__(256) void k_gemm2_mma(int M) {
    __shared__ __half sA[128 * SA];
    __shared__ __half sB[NCLS * SB2];

    int t    = threadIdx.x;
    int lane = t & 31;
    int wid  = t >> 5;
    int blockRow = blockIdx.x * 128;

    float acc[5][4];
#pragma unroll
    for (int ni = 0; ni < 5; ni++)
#pragma unroll
        for (int c = 0; c < 4; c++) acc[ni][c] = 0.f;

    for (int i = t; i < NCLS * (HID / 4); i += 256) {
        int n = i / (HID / 4);
        int q = i % (HID / 4);
        *(ull*)&sB[n * SB2 + q * 4] = *(const ull*)&g_w2t[(size_t)n * HID + q * 4];
    }

    const int lg = lane >> 2;
    const int lk = (lane & 3) * 2;
    const __half* a1 = (const __half*)g_a1f;

    for (int ch = 0; ch < 4; ch++) {
        int kt = ch * 32;
#pragma unroll
        for (int i = 0; i < 4; i++) {
            int f  = t + i * 256;
            int r  = f >> 3;
            int c4 = f & 7;
            int gr = blockRow + r;
            if (gr >= M) gr = M - 1;
            *(ull*)&sA[r * SA + c4 * 4] = *(const ull*)&a1[(size_t)gr * HID + kt + c4 * 4];
        }
        __syncthreads();

#pragma unroll
        for (int kk = 0; kk < 2; kk++) {
            int k0 = kk * 16 + lk;
            int r0 = wid * 16 + lg;
            uint32_t a[4];
            a[0] = *(const uint32_t*)&sA[r0 * SA + k0];
            a[1] = *(const uint32_t*)&sA[(r0 + 8) * SA + k0];
            a[2] = *(const uint32_t*)&sA[r0 * SA + k0 + 8];
            a[3] = *(const uint32_t*)&sA[(r0 + 8) * SA + k0 + 8];
            int kb = kt + kk * 16 + lk;
#pragma unroll
            for (int ni = 0; ni < 5; ni++) {
                int c0 = ni * 8 + lg;
                uint32_t b0 = *(const uint32_t*)&sB[c0 * SB2 + kb];
                uint32_t b1 = *(const uint32_t*)&sB[c0 * SB2 + kb + 8];
                MMA_F16(acc[ni], a, b0, b1);
            }
        }
        __syncthreads();
    }

    int r0 = blockRow + wid * 16 + (lane >> 2);
#pragma unroll
    for (int ni = 0; ni < 5; ni++) {
        int c2 = (ni * 8 + (lane & 3) * 2) >> 1;
        if (r0 < M)
            g_h2f[(size_t)r0 * (NCLS / 2) + c2] = __floats2half2_rn(acc[ni][0], acc[ni][1]);
        if (r0 + 8 < M)
            g_h2f[(size_t)(r0 + 8) * (NCLS / 2) + c2] = __floats2half2_rn(acc[ni][2], acc[ni][3]);
    }
}

// ------- Aggregation 2 + log_softmax: warp/node, x4-unrolled gather --------
__global__ void k_agg2(const float* __restrict__ b2, float* __restrict__ out, int n) {
    int w = (blockIdx.x * blockDim.x + threadIdx.x) >> 5;
    if (w >= n) return;
    int l = threadIdx.x & 31;
    bool act = (l < NCLS / 2);
    int lc = act ? l : 0;

    float di = g_dis[w];
    float dself = di * di;

    float2 acc = make_float2(0.f, 0.f);
    {
        float2 f = __half22float2(g_h2f[(size_t)w * (NCLS / 2) + lc]);
        acc.x = f.x * dself;
        acc.y = f.y * dself;
    }

    int beg = g_off[w], end = g_off[w + 1];
    int p = beg;
    for (; p + 4 <= end; p += 4) {
        int   s0i = g_esrc[p],     s1i = g_esrc[p + 1];
        int   s2i = g_esrc[p + 2], s3i = g_esrc[p + 3];
        float w0 = g_enrm[p],      w1 = g_enrm[p + 1];
        float w2 = g_enrm[p + 2],  w3 = g_enrm[p + 3];
        float2 f0 = __half22float2(g_h2f[(size_t)s0i * (NCLS / 2) + lc]);
        float2 f1 = __half22float2(g_h2f[(size_t)s1i * (NCLS / 2) + lc]);
        float2 f2 = __half22float2(g_h2f[(size_t)s2i * (NCLS / 2) + lc]);
        float2 f3 = __half22float2(g_h2f[(size_t)s3i * (NCLS / 2) + lc]);
        acc.x = fmaf(f0.x, w0, acc.x); acc.y = fmaf(f0.y, w0, acc.y);
        acc.x = fmaf(f1.x, w1, acc.x); acc.y = fmaf(f1.y, w1, acc.y);
        acc.x = fmaf(f2.x, w2, acc.x); acc.y = fmaf(f2.y, w2, acc.y);
        acc.x = fmaf(f3.x, w3, acc.x); acc.y = fmaf(f3.y, w3, acc.y);
    }
    for (; p < end; p++) {
        int   s  = g_esrc[p];
        float wt = g_enrm[p];
        float2 f = __half22float2(g_h2f[(size_t)s * (NCLS / 2) + lc]);
        acc.x = fmaf(f.x, wt, acc.x);
        acc.y = fmaf(f.y, wt, acc.y);
    }
    if (act) {
        acc.x += b2[2 * l];
        acc.y += b2[2 * l + 1];
    }

    float m = act ? fmaxf(acc.x, acc.y) : -1e30f;
#pragma unroll
    for (int o = 16; o >= 1; o >>= 1) m = fmaxf(m, __shfl_xor_sync(0xffffffffu, m, o));
    float e = act ? (expf(acc.x - m) + expf(acc.y - m)) : 0.f;
#pragma unroll
    for (int o = 16; o >= 1; o >>= 1) e += __shfl_xor_sync(0xffffffffu, e, o);
    float lse = m + logf(e);

    if (act) {
        out[(size_t)w * NCLS + 2 * l]     = acc.x - lse;
        out[(size_t)w * NCLS + 2 * l + 1] = acc.y - lse;
    }
}

// --------------------------------- launch ----------------------------------
// Fork-join: CSR build on side stream s1, overlapped with wconv+gemm1 on the
// main stream. Submission order keeps gemm1 as kernel #4 (profiler slot).
extern "C" void kernel_launch(void* const* d_in, const int* in_sizes, int n_in,
                              void* d_out, int out_size) {
    const float* x  = (const float*)d_in[0];
    const int*   ei = (const int*)d_in[1];
    const float* W1 = (const float*)d_in[2];
    const float* b1 = (const float*)d_in[3];
    const float* W2 = (const float*)d_in[4];
    const float* b2 = (const float*)d_in[5];
    float*       out = (float*)d_out;

    int N = in_sizes[0] / FIN;       // 100000
    int E = in_sizes[1] / 2;         // 1600000
    int nb = (N + 1023) / 1024;

    cudaFuncSetAttribute(k_gemm1_mma, cudaFuncAttributeMaxDynamicSharedMemorySize, G1SM);

    k_wconv<<<(FIN * HID + 255) / 256, 256>>>(W1);                    // #1 (s0)

    // fork: CSR build chain on s1
    cudaEventRecord(g_se.e1, 0);
    cudaStreamWaitEvent(g_se.s1, g_se.e1, 0);
    k_probe<<<1, 1, 0, g_se.s1>>>((const unsigned*)d_in[1]);          // #2 (s1)
    k_init<<<(N + 255) / 256, 256, 0, g_se.s1>>>(N);                  // #3 (s1)

    k_gemm1_mma<<<(N + 127) / 128, 256, G1SM>>>(x, N);                // #4 (s0) <- profiled

    k_hist<<<(E + 255) / 256, 256, 0, g_se.s1>>>(ei, E);              // s1
    k_scanA<<<nb, 1024, 0, g_se.s1>>>(N);                             // s1
    k_scanB<<<1, 128, 0, g_se.s1>>>(nb);                              // s1
    k_scanC<<<nb, 1024, 0, g_se.s1>>>(N);                             // s1
    k_scatter<<<(E + 255) / 256, 256, 0, g_se.s1>>>(ei, E);           // s1

    k_wconv2<<<(HID * NCLS + 255) / 256, 256>>>(W2);                  // s0

    // join: agg1 needs gemm1 (s0) + scatter (s1)
    cudaEventRecord(g_se.e2, g_se.s1);
    cudaStreamWaitEvent(0, g_se.e2, 0);

    k_agg1<<<(N * 32 + 255) / 256, 256>>>(b1, N);                     // s0
    k_gemm2_mma<<<(N + 127) / 128, 256>>>(N);                         // s0
    k_agg2<<<(N * 32 + 255) / 256, 256>>>(b2, out, N);                // s0
}